// round 2
// baseline (speedup 1.0000x reference)
#include <cuda_runtime.h>
#include <math.h>

#define BB 16
#define NN 8192
#define DD 64
#define SS 1024
#define NSAMP 32

// ---------------- device scratch (no allocations allowed) ----------------
__device__ int   g_fpsidx[BB*SS];
__device__ int   g_gidx[BB*SS*NSAMP];
__device__ float g_xyzt[BB*NN*4];          // (b,p,{x,y,z,0})
__device__ float g_ptst[BB*NN*DD];         // points transposed (b,p,c)
__device__ float g_xpost[(size_t)BB*SS*DD*NSAMP]; // post-mlp activations [tile][c][j]
__device__ float g_ysum[BB*64];            // ECA mean accumulators
__device__ float g_wp[BB*64*128];          // folded ECA weights [b][c*128+o]

// ---------------- prep: xyz transpose + ysum zero ----------------
__global__ void prep_kernel(const float* __restrict__ xyz){
    int gp = blockIdx.x*256 + threadIdx.x;      // 0..131071
    int b = gp >> 13, p = gp & (NN-1);
    float x = xyz[b*3*NN + p];
    float y = xyz[b*3*NN + NN + p];
    float z = xyz[b*3*NN + 2*NN + p];
    reinterpret_cast<float4*>(g_xyzt)[b*NN+p] = make_float4(x,y,z,0.f);
    if (gp < BB*64) g_ysum[gp] = 0.f;
}

// ---------------- points transpose (B,C,N) -> (B,N,C) ----------------
__global__ void transpose_kernel(const float* __restrict__ pts){
    __shared__ float tile[32][33];
    int b = blockIdx.z, c0 = blockIdx.y*32, p0 = blockIdx.x*32;
    int tx = threadIdx.x, ty = threadIdx.y;
    #pragma unroll
    for (int i=ty;i<32;i+=8)
        tile[i][tx] = pts[(size_t)b*DD*NN + (size_t)(c0+i)*NN + p0+tx];
    __syncthreads();
    #pragma unroll
    for (int i=ty;i<32;i+=8)
        g_ptst[(size_t)b*NN*DD + (size_t)(p0+i)*DD + c0+tx] = tile[tx][i];
}

// ---------------- FPS: 1 block per batch, 1024 threads, 8 pts/thread ----------------
__global__ __launch_bounds__(1024) void fps_kernel(const float* __restrict__ xyz,
                                                   float* __restrict__ out){
    extern __shared__ float sh[];               // [3*NN] coords + reduction slots
    unsigned* rbits = (unsigned*)(sh + 3*NN);
    unsigned* ridx  = rbits + 32;
    volatile int* rfar = (int*)(ridx + 32);
    int b = blockIdx.x;
    int t = threadIdx.x, lane = t&31, warp = t>>5;
    const float* xb = xyz + (size_t)b*3*NN;
    for (int p=t; p<NN; p+=1024){
        sh[p]        = xb[p];
        sh[NN+p]     = xb[NN+p];
        sh[2*NN+p]   = xb[2*NN+p];
    }
    __syncthreads();
    int base = t*8;
    float px[8],py[8],pz[8],dist[8];
    #pragma unroll
    for (int i=0;i<8;i++){
        px[i]=sh[base+i]; py[i]=sh[NN+base+i]; pz[i]=sh[2*NN+base+i];
        dist[i]=1e10f;
    }
    if (t==0) g_fpsidx[b*SS] = 0;
    int far = 0;
    for (int it=1; it<SS; it++){
        float cx = sh[far], cy = sh[NN+far], cz = sh[2*NN+far];
        float best = -1.f; int bi = base;
        #pragma unroll
        for (int i=0;i<8;i++){
            float dx = px[i]-cx, dy = py[i]-cy, dz = pz[i]-cz;
            float d  = fmaf(dz,dz, fmaf(dy,dy, dx*dx));
            float nd = fminf(dist[i], d);
            dist[i] = nd;
            if (nd > best){ best = nd; bi = base+i; }   // first-index tie-break
        }
        unsigned bbits = __float_as_uint(best);
        unsigned wmax = __reduce_max_sync(0xffffffffu, bbits);
        unsigned cand = (bbits==wmax) ? (unsigned)bi : 0xffffffffu;
        unsigned wmin = __reduce_min_sync(0xffffffffu, cand);
        if (lane==0){ rbits[warp]=wmax; ridx[warp]=wmin; }
        __syncthreads();
        if (warp==0){
            unsigned rb = rbits[lane], ri = ridx[lane];
            unsigned m2 = __reduce_max_sync(0xffffffffu, rb);
            unsigned c2 = (rb==m2) ? ri : 0xffffffffu;
            unsigned fi = __reduce_min_sync(0xffffffffu, c2);
            if (lane==0){ *rfar = (int)fi; g_fpsidx[b*SS+it] = (int)fi; }
        }
        __syncthreads();
        far = *rfar;
    }
    __syncthreads();
    if (t < SS){
        int ci = g_fpsidx[b*SS+t];
        out[b*3*SS + t]        = sh[ci];
        out[b*3*SS + SS + t]   = sh[NN+ci];
        out[b*3*SS + 2*SS + t] = sh[2*NN+ci];
    }
}

// ---------------- ball query: 1 warp per (b,s), first-32-in-range ----------------
__global__ __launch_bounds__(256) void ballq_kernel(const float* __restrict__ xyz){
    int wg   = blockIdx.x*8 + (threadIdx.x>>5);
    int lane = threadIdx.x & 31;
    int b = wg >> 10, s = wg & (SS-1);
    const float* xb = xyz + (size_t)b*3*NN;
    int ci = g_fpsidx[b*SS+s];
    float cx = xb[ci], cy = xb[NN+ci], cz = xb[2*NN+ci];
    int cnt = 0, first = -1;
    int bs = (b*SS+s)*NSAMP;
    for (int ch=0; ch<NN/32; ch++){
        int p = ch*32 + lane;
        float dx = xb[p]-cx, dy = xb[NN+p]-cy, dz = xb[2*NN+p]-cz;
        float d  = fmaf(dz,dz, fmaf(dy,dy, dx*dx));
        bool in = d < 0.04f;
        unsigned m = __ballot_sync(0xffffffffu, in);
        if (first < 0 && m) first = ch*32 + __ffs(m) - 1;
        int pos = cnt + __popc(m & ((1u<<lane)-1u));
        if (in && pos < NSAMP) g_gidx[bs+pos] = p;
        cnt += __popc(m);
        if (cnt >= NSAMP) break;
    }
    if (lane >= cnt) g_gidx[bs+lane] = first;   // pad with first valid idx
}

// ---------------- fused gather + attention + MLP ----------------
// smem float layout
#define W2OFF 0
#define M0OFF 4096
#define M1OFF 8192
#define BOFF  12288
#define W1OFF 12480
#define B1OFF 12992
#define W0OFF 13056
#define B0OFF 13080
#define STOFF 13088
#define K3_SMEM_FLOATS (13088 + 8*2048)

__global__ __launch_bounds__(256) void k3_kernel(
    const float* __restrict__ xyz,
    const float* __restrict__ aw0, const float* __restrict__ ab0,
    const float* __restrict__ as0, const float* __restrict__ at0,
    const float* __restrict__ aw1, const float* __restrict__ ab1,
    const float* __restrict__ as1, const float* __restrict__ at1,
    const float* __restrict__ aw2, const float* __restrict__ ab2,
    const float* __restrict__ as2, const float* __restrict__ at2,
    const float* __restrict__ mw0, const float* __restrict__ mb0,
    const float* __restrict__ ms0, const float* __restrict__ mt0,
    const float* __restrict__ mw1, const float* __restrict__ mb1,
    const float* __restrict__ ms1, const float* __restrict__ mt1)
{
    extern __shared__ float sm[];
    int tid = threadIdx.x, lane = tid&31, warp = tid>>5;
    int b = blockIdx.y, s = blockIdx.x*8 + warp;

    // fold BN into transposed weights: W'[k*64+o] = s[o]*W[o][k]
    for (int i=tid;i<4096;i+=256){
        int k=i>>6, o=i&63;
        sm[W2OFF+i] = as2[o]*aw2[o*64+k];
        sm[M0OFF+i] = ms0[o]*mw0[o*64+k];
        sm[M1OFF+i] = ms1[o]*mw1[o*64+k];
    }
    if (tid<64){
        sm[BOFF+tid]      = fmaf(as2[tid],ab2[tid],at2[tid]);
        sm[BOFF+64+tid]   = fmaf(ms0[tid],mb0[tid],mt0[tid]);
        sm[BOFF+128+tid]  = fmaf(ms1[tid],mb1[tid],mt1[tid]);
        sm[B1OFF+tid]     = fmaf(as1[tid],ab1[tid],at1[tid]);
    }
    // FIX R1: W1 has 512 entries but blockDim is 256 — must stride, not guard.
    for (int i=tid;i<512;i+=256){
        int ii=i>>6, c=i&63;
        sm[W1OFF+i] = as1[c]*aw1[c*8+ii];
    }
    if (tid<24)  sm[W0OFF+tid] = as0[tid/3]*aw0[tid];
    if (tid<8)   sm[B0OFF+tid] = fmaf(as0[tid],ab0[tid],at0[tid]);
    __syncthreads();

    int tile = b*SS + s;
    int p  = g_gidx[tile*NSAMP + lane];
    int ci = g_fpsidx[tile];
    const float* xb = xyz + (size_t)b*3*NN;
    float cx = xb[ci], cy = xb[NN+ci], cz = xb[2*NN+ci];
    float4 pt = reinterpret_cast<const float4*>(g_xyzt)[b*NN+p];
    float gx = pt.x-cx, gy = pt.y-cy, gz = pt.z-cz;

    // pos path: 3 -> 8 (relu) -> 64
    float p8[8];
    #pragma unroll
    for (int o=0;o<8;o++){
        float pre = fmaf(gz, sm[W0OFF+o*3+2],
                    fmaf(gy, sm[W0OFF+o*3+1],
                    fmaf(gx, sm[W0OFF+o*3+0], sm[B0OFF+o])));
        p8[o] = fmaxf(pre, 0.f);
    }
    float* stg = sm + STOFF + warp*2048;
    for (int o8=0;o8<64;o8+=8){
        float acc[8];
        #pragma unroll
        for (int j=0;j<8;j++) acc[j]=sm[B1OFF+o8+j];
        #pragma unroll
        for (int i=0;i<8;i++){
            float pv = p8[i];
            #pragma unroll
            for (int j=0;j<8;j++) acc[j] = fmaf(pv, sm[W1OFF + i*64 + o8 + j], acc[j]);
        }
        #pragma unroll
        for (int j=0;j<8;j++) stg[(o8+j)*32+lane] = acc[j];
    }

    // gather features + add pos
    float v[64];
    const float4* prow = reinterpret_cast<const float4*>(g_ptst + (size_t)(b*NN+p)*64);
    #pragma unroll
    for (int q=0;q<16;q++){
        float4 f = prow[q];
        v[q*4+0] = f.x + stg[(q*4+0)*32+lane];
        v[q*4+1] = f.y + stg[(q*4+1)*32+lane];
        v[q*4+2] = f.z + stg[(q*4+2)*32+lane];
        v[q*4+3] = f.w + stg[(q*4+3)*32+lane];
    }

    // 3 layers of 64x64 matvec (layer 0: bn only; layers 1,2: bn+relu)
    for (int l=0;l<3;l++){
        const float* W  = sm + l*4096;
        const float* bv = sm + BOFF + l*64;
        for (int o8=0;o8<64;o8+=8){
            float acc[8];
            #pragma unroll
            for (int j=0;j<8;j++) acc[j] = bv[o8+j];
            #pragma unroll
            for (int k=0;k<64;k++){
                float vk = v[k];
                #pragma unroll
                for (int j=0;j<8;j++) acc[j] = fmaf(vk, W[k*64+o8+j], acc[j]);
            }
            #pragma unroll
            for (int j=0;j<8;j++){
                float h = acc[j];
                if (l>0) h = fmaxf(h, 0.f);
                stg[(o8+j)*32+lane] = h;
            }
        }
        #pragma unroll
        for (int k=0;k<64;k++) v[k] = stg[k*32+lane];
    }

    // write activations + channel mean partials
    float* xo = g_xpost + (size_t)tile*2048;
    #pragma unroll
    for (int c=0;c<64;c++) xo[c*32+lane] = v[c];
    float sa = 0.f, sb = 0.f;
    #pragma unroll
    for (int c=0;c<64;c++){
        float t = v[c];
        t += __shfl_xor_sync(0xffffffffu, t, 16);
        t += __shfl_xor_sync(0xffffffffu, t, 8);
        t += __shfl_xor_sync(0xffffffffu, t, 4);
        t += __shfl_xor_sync(0xffffffffu, t, 2);
        t += __shfl_xor_sync(0xffffffffu, t, 1);
        if (lane == (c&31)){ if (c < 32) sa = t; else sb = t; }
    }
    atomicAdd(&g_ysum[b*64+lane],      sa);
    atomicAdd(&g_ysum[b*64+32+lane],   sb);
}

// ---------------- ECA: mean -> 1d conv -> sigmoid -> fold into weights ----------------
__global__ void k4_kernel(const float* __restrict__ eca_k,
                          const float* __restrict__ eca_w,
                          const float* __restrict__ eca_s){
    __shared__ float ys[64], sg[64];
    int b = blockIdx.x, tid = threadIdx.x;   // blockDim = 128, tid = output channel o
    if (tid < 64) ys[tid] = g_ysum[b*64+tid] * (1.f/32768.f);
    __syncthreads();
    if (tid < 64){
        float k0 = eca_k[0], k1 = eca_k[1], k2 = eca_k[2];
        float c = k0*(tid>0 ? ys[tid-1] : 0.f) + k1*ys[tid] + k2*(tid<63 ? ys[tid+1] : 0.f);
        sg[tid] = 1.f/(1.f + expf(-c));
    }
    __syncthreads();
    float es = eca_s[tid];
    for (int c=0;c<64;c++)
        g_wp[b*8192 + c*128 + tid] = eca_w[tid*64+c]*sg[c]*es;
}

// ---------------- final conv 64->128 + bn + max pool over ns ----------------
__global__ __launch_bounds__(256) void k5_kernel(const float* __restrict__ eca_b,
                                                 const float* __restrict__ eca_s,
                                                 const float* __restrict__ eca_t,
                                                 float* __restrict__ out){
    __shared__ float W[8192];
    __shared__ float bv[128];
    int tid = threadIdx.x, lane = tid&31, warp = tid>>5;
    int b = blockIdx.y, s = blockIdx.x*8 + warp;
    for (int i=tid;i<8192;i+=256) W[i] = g_wp[b*8192+i];
    if (tid<128) bv[tid] = fmaf(eca_s[tid], eca_b[tid], eca_t[tid]);
    __syncthreads();
    int tile = b*SS + s;
    const float* xp = g_xpost + (size_t)tile*2048;
    float v[64];
    #pragma unroll
    for (int c=0;c<64;c++) v[c] = xp[c*32+lane];
    float* fo = out + BB*3*SS + (size_t)b*128*SS;
    for (int o8=0;o8<128;o8+=8){
        float acc[8];
        #pragma unroll
        for (int j=0;j<8;j++) acc[j] = bv[o8+j];
        #pragma unroll
        for (int k=0;k<64;k++){
            float vk = v[k];
            #pragma unroll
            for (int j=0;j<8;j++) acc[j] = fmaf(vk, W[k*128+o8+j], acc[j]);
        }
        #pragma unroll
        for (int j=0;j<8;j++){
            float m = acc[j];
            m = fmaxf(m, __shfl_xor_sync(0xffffffffu, m, 16));
            m = fmaxf(m, __shfl_xor_sync(0xffffffffu, m, 8));
            m = fmaxf(m, __shfl_xor_sync(0xffffffffu, m, 4));
            m = fmaxf(m, __shfl_xor_sync(0xffffffffu, m, 2));
            m = fmaxf(m, __shfl_xor_sync(0xffffffffu, m, 1));
            if (lane == ((o8+j)&31)) fo[(o8+j)*SS + s] = m;
        }
    }
}

// ---------------- launcher ----------------
extern "C" void kernel_launch(void* const* d_in, const int* in_sizes, int n_in,
                              void* d_out, int out_size){
    const float* xyz = (const float*)d_in[0];
    const float* pts = (const float*)d_in[1];
    float* out = (float*)d_out;

    cudaFuncSetAttribute(fps_kernel, cudaFuncAttributeMaxDynamicSharedMemorySize, 3*NN*4 + 512);
    cudaFuncSetAttribute(k3_kernel,  cudaFuncAttributeMaxDynamicSharedMemorySize, K3_SMEM_FLOATS*4);

    prep_kernel<<<512,256>>>(xyz);
    transpose_kernel<<<dim3(256,2,16), dim3(32,8)>>>(pts);
    fps_kernel<<<BB,1024, 3*NN*4 + 512>>>(xyz, out);
    ballq_kernel<<<2048,256>>>(xyz);
    k3_kernel<<<dim3(128,16),256, K3_SMEM_FLOATS*4>>>(
        xyz,
        (const float*)d_in[2],  (const float*)d_in[3],  (const float*)d_in[4],  (const float*)d_in[5],
        (const float*)d_in[6],  (const float*)d_in[7],  (const float*)d_in[8],  (const float*)d_in[9],
        (const float*)d_in[10], (const float*)d_in[11], (const float*)d_in[12], (const float*)d_in[13],
        (const float*)d_in[14], (const float*)d_in[15], (const float*)d_in[16], (const float*)d_in[17],
        (const float*)d_in[18], (const float*)d_in[19], (const float*)d_in[20], (const float*)d_in[21]);
    k4_kernel<<<BB,128>>>((const float*)d_in[22], (const float*)d_in[23], (const float*)d_in[25]);
    k5_kernel<<<dim3(128,16),256>>>((const float*)d_in[24], (const float*)d_in[25],
                                    (const float*)d_in[26], out);
}